// round 15
// baseline (speedup 1.0000x reference)
#include <cuda_runtime.h>
#include <cuda_bf16.h>
#include <math.h>
#include <cstdint>

#define BB 32
#define AA 1024
#define FF 128
#define NN (BB*AA)

// ================= scratch =================
__device__ float g_u2[2][FF];
__device__ float g_bk2[2];
__device__ float g_wow[FF];
__device__ float g_num[NN];
__device__ float g_numpart[NN/256];
__device__ float g_ezwe[NN];
__device__ float4 g_xyzq[NN];       // packed (x, y, z, pred_q) written by k2
__device__ float g_partial[BB*16];
__device__ int   g_cnt[BB];
// W1^T / W2^T as bf16, layout Wt[n][k], row stride 136 (272 B): 128*136*2 = 34816 B each
__device__ uint4 g_W1bf4[2176];
__device__ uint4 g_W2bf4[2176];

__device__ __forceinline__ float tanha(float x) {
    float r;
    asm("tanh.approx.f32 %0, %1;" : "=f"(r) : "f"(x));
    return r;
}
__device__ __forceinline__ float fsilu(float x) {   // x*sigmoid(x) = 0.5x(1+tanh(x/2))
    float h = 0.5f * x;
    return fmaf(h, tanha(h), h);
}
__device__ __forceinline__ float rsqa(float x) {    // exactly one MUFU.RSQ
    float r;
    asm("rsqrt.approx.f32 %0, %1;" : "=f"(r) : "f"(x));
    return r;
}
__device__ __forceinline__ uint32_t packbf(float lo, float hi) {
    uint32_t r;
    asm("cvt.rn.satfinite.bf16x2.f32 %0, %1, %2;" : "=r"(r) : "f"(hi), "f"(lo));
    return r;
}
__device__ __forceinline__ uint32_t smem_u32(const void* p) {
    uint32_t a;
    asm("{ .reg .u64 t; cvta.to.shared.u64 t, %1; cvt.u32.u64 %0, t; }" : "=r"(a) : "l"(p));
    return a;
}
__device__ __forceinline__ void ldsm_x4(uint32_t& r0, uint32_t& r1, uint32_t& r2, uint32_t& r3,
                                        uint32_t addr) {
    asm volatile("ldmatrix.sync.aligned.m8n8.x4.shared.b16 {%0,%1,%2,%3}, [%4];"
                 : "=r"(r0), "=r"(r1), "=r"(r2), "=r"(r3) : "r"(addr));
}
__device__ __forceinline__ void mma16816(float* d, const uint32_t* a, uint32_t b0, uint32_t b1) {
    asm volatile("mma.sync.aligned.m16n8k16.row.col.f32.bf16.bf16.f32 "
                 "{%0,%1,%2,%3}, {%4,%5,%6,%7}, {%8,%9}, {%0,%1,%2,%3};"
                 : "+f"(d[0]), "+f"(d[1]), "+f"(d[2]), "+f"(d[3])
                 : "r"(a[0]), "r"(a[1]), "r"(a[2]), "r"(a[3]), "r"(b0), "r"(b1));
}

// ---------------- K0f: projected vectors only (weight convert lives in k1) ----
__global__ void k0f(const float* __restrict__ W_lin, const float* __restrict__ b_lin,
                    const float* __restrict__ kp, const float* __restrict__ km,
                    const float* __restrict__ Wout, const float* __restrict__ w_e) {
    int blk = blockIdx.x, tid = threadIdx.x;
    __shared__ float r0[256], r1[256], r2[256];
    if (blk < 128) {
        int g = blk;
        float a0 = 0.f, a1 = 0.f, a2 = 0.f;
        if (tid < 128) {
            float w = W_lin[g*FF + tid];
            a0 = w * kp[tid];
            a1 = w * km[tid];
            a2 = Wout[g*FF + tid] * w_e[tid];
        }
        r0[tid] = a0; r1[tid] = a1; r2[tid] = a2;
        __syncthreads();
        for (int off = 128; off > 0; off >>= 1) {
            if (tid < off) { r0[tid] += r0[tid+off]; r1[tid] += r1[tid+off]; r2[tid] += r2[tid+off]; }
            __syncthreads();
        }
        if (tid == 0) { g_u2[0][g] = r0[0]; g_u2[1][g] = r1[0]; g_wow[g] = r2[0]; }
        return;
    }
    float a0 = 0.f, a1 = 0.f;
    if (tid < 128) { float bl = b_lin[tid]; a0 = bl * kp[tid]; a1 = bl * km[tid]; }
    r0[tid] = a0; r1[tid] = a1;
    __syncthreads();
    for (int off = 128; off > 0; off >>= 1) {
        if (tid < off) { r0[tid] += r0[tid+off]; r1[tid] += r1[tid+off]; }
        __syncthreads();
    }
    if (tid == 0) { g_bk2[0] = r0[0]; g_bk2[1] = r1[0]; }
}

// ---------------- K1: row dots (blocks 0-127) + weight convert (128-191) -----
__global__ void k1_fused(const float* __restrict__ e_z, const float* __restrict__ charge,
                         const float* __restrict__ w_e,
                         const float* __restrict__ W1, const float* __restrict__ W2) {
    int bb = blockIdx.x;
    int tid = threadIdx.x;
    if (bb >= 128) {                     // weight-convert blocks (independent of k0f)
        int i = (bb - 128) * 256 + tid;  // 0..16383
        int k = i >> 7, n = i & 127;
        int off = n*136 + k;
        ((__nv_bfloat16*)g_W1bf4)[off] = __float2bfloat16(W1[k*FF + n]);
        ((__nv_bfloat16*)g_W2bf4)[off] = __float2bfloat16(W2[k*FF + n]);
        return;
    }
    __shared__ float s_u[FF];
    __shared__ float s_we[FF];
    __shared__ float s_ws[8];
    int b  = bb >> 2;
    int wid = tid >> 5, lane = tid & 31;
    if (bb == 0 && tid < BB) g_cnt[tid] = 0;     // reset k4 completion counters
    float c = charge[b];
    int sgn = (c >= 0.0f) ? 0 : 1;
    if (tid < FF) { s_u[tid] = g_u2[sgn][tid]; s_we[tid] = w_e[tid]; }
    __syncthreads();

    float4 uu = ((const float4*)s_u)[lane];
    float4 ww = ((const float4*)s_we)[lane];
    float bk = g_bk2[sgn];
    const float inv_sqrtF = 0.08838834764831845f;
    const float4* ez = (const float4*)e_z;
    int row0 = bb*256 + wid*32;
    float wsum = 0.f;

    #pragma unroll 1
    for (int rr = 0; rr < 32; rr += 2) {
        int n0 = row0 + rr, n1 = n0 + 1;
        float4 va = ez[(size_t)n0*32 + lane];
        float4 vb = ez[(size_t)n1*32 + lane];
        float d1a = va.x*uu.x + va.y*uu.y + va.z*uu.z + va.w*uu.w;
        float d2a = va.x*ww.x + va.y*ww.y + va.z*ww.z + va.w*ww.w;
        float d1b = vb.x*uu.x + vb.y*uu.y + vb.z*uu.z + vb.w*uu.w;
        float d2b = vb.x*ww.x + vb.y*ww.y + vb.z*ww.z + vb.w*ww.w;
        #pragma unroll
        for (int off = 16; off > 0; off >>= 1) {
            d1a += __shfl_xor_sync(0xffffffffu, d1a, off);
            d2a += __shfl_xor_sync(0xffffffffu, d2a, off);
            d1b += __shfl_xor_sync(0xffffffffu, d1b, off);
            d2b += __shfl_xor_sync(0xffffffffu, d2b, off);
        }
        float arga = (d1a + bk) * inv_sqrtF;
        float numa = fmaxf(arga, 0.f) + log1pf(expf(-fabsf(arga)));
        float argb = (d1b + bk) * inv_sqrtF;
        float numb = fmaxf(argb, 0.f) + log1pf(expf(-fabsf(argb)));
        wsum += numa + numb;
        if (lane == 0) {
            g_num[n0] = numa; g_ezwe[n0] = d2a;
            g_num[n1] = numb; g_ezwe[n1] = d2b;
        }
    }
    if (lane == 0) s_ws[wid] = wsum;
    __syncthreads();
    if (tid == 0) {
        float s = 0.f;
        #pragma unroll
        for (int i = 0; i < 8; i++) s += s_ws[i];
        g_numpart[bb] = s;
    }
}

// ---------------- K2: HMMA res-MLP, 4 warps x 2 stripes (B-fragment reuse) ----
// smem: sW1 [0,34816) sW2 [34816,69632) s_a 69632 s_v 70144 s_wow 70656; total 71168
#define K2_SMEM 71168
__global__ void __launch_bounds__(128, 2)
k2_mma(const float* __restrict__ charge, const int* __restrict__ z,
       const float* __restrict__ q_tab,
       const float* __restrict__ vp, const float* __restrict__ vm,
       const float* __restrict__ xyz) {
    extern __shared__ char smem[];
    float* s_a   = (float*)(smem + 69632);
    float* s_v   = (float*)(smem + 70144);
    float* s_wow = (float*)(smem + 70656);
    uint32_t sb = smem_u32(smem);

    int tid = threadIdx.x, wid = tid >> 5, lane = tid & 31;
    int m0 = blockIdx.x * 128;
    int b = m0 >> 10;
    float c = charge[b];
    const float* v = (c >= 0.f) ? vp : vm;

    uint4* dst1 = (uint4*)smem;
    uint4* dst2 = (uint4*)(smem + 34816);
    for (int i = tid; i < 2176; i += 128) { dst1[i] = g_W1bf4[i]; dst2[i] = g_W2bf4[i]; }
    {
        float tot = g_numpart[b*4] + g_numpart[b*4+1] + g_numpart[b*4+2] + g_numpart[b*4+3];
        s_a[tid]   = c * g_num[m0 + tid] / tot;
        s_v[tid]   = v[tid];
        s_wow[tid] = g_wow[tid];
    }
    __syncthreads();

    int quad = lane >> 2, qt = lane & 3;
    int mrowA = wid * 32 + quad;          // stripe A rows (c0/c1; +8 for c2/c3)
    int mrowB = mrowA + 16;               // stripe B rows
    float amA0 = s_a[mrowA], amA8 = s_a[mrowA + 8];
    float amB0 = s_a[mrowB], amB8 = s_a[mrowB + 8];

    int rl = ((lane >> 4) << 3) | (lane & 7);
    uint32_t boff = (uint32_t)(rl * 272 + ((lane >> 3) & 1) * 16);

    // GEMM1 A fragments (both stripes): X = silu(a*v), analytic
    uint32_t afA[8][4], afB[8][4];
    #pragma unroll
    for (int s = 0; s < 8; s++) {
        int k0 = s*16 + qt*2;
        float v0 = s_v[k0], v1 = s_v[k0+1], v8 = s_v[k0+8], v9 = s_v[k0+9];
        afA[s][0] = packbf(fsilu(amA0*v0), fsilu(amA0*v1));
        afA[s][1] = packbf(fsilu(amA8*v0), fsilu(amA8*v1));
        afA[s][2] = packbf(fsilu(amA0*v8), fsilu(amA0*v9));
        afA[s][3] = packbf(fsilu(amA8*v8), fsilu(amA8*v9));
        afB[s][0] = packbf(fsilu(amB0*v0), fsilu(amB0*v1));
        afB[s][1] = packbf(fsilu(amB8*v0), fsilu(amB8*v1));
        afB[s][2] = packbf(fsilu(amB0*v8), fsilu(amB0*v9));
        afB[s][3] = packbf(fsilu(amB8*v8), fsilu(amB8*v9));
    }

    // ---- GEMM1 in two n-halves; each LDSM feeds 4 MMAs (2 nt x 2 stripes) ----
    float accA[8][4], accB[8][4];
    #pragma unroll
    for (int h = 0; h < 2; h++) {
        #pragma unroll
        for (int l = 0; l < 8; l++)
            #pragma unroll
            for (int i = 0; i < 4; i++) { accA[l][i] = 0.f; accB[l][i] = 0.f; }
        #pragma unroll
        for (int s = 0; s < 8; s++) {
            #pragma unroll
            for (int npl = 0; npl < 4; npl++) {
                int np = h*4 + npl;
                uint32_t b0, b1, b2, b3;
                ldsm_x4(b0, b1, b2, b3, sb + (uint32_t)(np*4352 + s*32) + boff);
                mma16816(accA[2*npl],   afA[s], b0, b1);
                mma16816(accA[2*npl+1], afA[s], b2, b3);
                mma16816(accB[2*npl],   afB[s], b0, b1);
                mma16816(accB[2*npl+1], afB[s], b2, b3);
            }
        }
        // chain: af2 = silu(h1) fragments (overwrite af in place)
        #pragma unroll
        for (int ss = 0; ss < 4; ss++) {
            int s2 = h*4 + ss;
            uint32_t nA0 = packbf(fsilu(accA[2*ss][0]),   fsilu(accA[2*ss][1]));
            uint32_t nA1 = packbf(fsilu(accA[2*ss][2]),   fsilu(accA[2*ss][3]));
            uint32_t nA2 = packbf(fsilu(accA[2*ss+1][0]), fsilu(accA[2*ss+1][1]));
            uint32_t nA3 = packbf(fsilu(accA[2*ss+1][2]), fsilu(accA[2*ss+1][3]));
            uint32_t nB0 = packbf(fsilu(accB[2*ss][0]),   fsilu(accB[2*ss][1]));
            uint32_t nB1 = packbf(fsilu(accB[2*ss][2]),   fsilu(accB[2*ss][3]));
            uint32_t nB2 = packbf(fsilu(accB[2*ss+1][0]), fsilu(accB[2*ss+1][1]));
            uint32_t nB3 = packbf(fsilu(accB[2*ss+1][2]), fsilu(accB[2*ss+1][3]));
            afA[s2][0] = nA0; afA[s2][1] = nA1; afA[s2][2] = nA2; afA[s2][3] = nA3;
            afB[s2][0] = nB0; afB[s2][1] = nB1; afB[s2][2] = nB2; afB[s2][3] = nB3;
        }
    }

    // ---- GEMM2 in two n-halves + fused epilogue ----
    float pA0 = 0.f, pA8 = 0.f, pB0 = 0.f, pB8 = 0.f;
    #pragma unroll
    for (int h = 0; h < 2; h++) {
        #pragma unroll
        for (int l = 0; l < 8; l++)
            #pragma unroll
            for (int i = 0; i < 4; i++) { accA[l][i] = 0.f; accB[l][i] = 0.f; }
        #pragma unroll
        for (int s = 0; s < 8; s++) {
            #pragma unroll
            for (int npl = 0; npl < 4; npl++) {
                int np = h*4 + npl;
                uint32_t b0, b1, b2, b3;
                ldsm_x4(b0, b1, b2, b3, sb + (uint32_t)(34816 + np*4352 + s*32) + boff);
                mma16816(accA[2*npl],   afA[s], b0, b1);
                mma16816(accA[2*npl+1], afA[s], b2, b3);
                mma16816(accB[2*npl],   afB[s], b0, b1);
                mma16816(accB[2*npl+1], afB[s], b2, b3);
            }
        }
        #pragma unroll
        for (int ntl = 0; ntl < 8; ntl++) {
            int n = (h*8 + ntl)*8 + qt*2;
            float vv0 = s_v[n], vv1 = s_v[n+1], w0 = s_wow[n], w1 = s_wow[n+1];
            pA0 += fsilu(amA0*vv0 + accA[ntl][0]) * w0 + fsilu(amA0*vv1 + accA[ntl][1]) * w1;
            pA8 += fsilu(amA8*vv0 + accA[ntl][2]) * w0 + fsilu(amA8*vv1 + accA[ntl][3]) * w1;
            pB0 += fsilu(amB0*vv0 + accB[ntl][0]) * w0 + fsilu(amB0*vv1 + accB[ntl][1]) * w1;
            pB8 += fsilu(amB8*vv0 + accB[ntl][2]) * w0 + fsilu(amB8*vv1 + accB[ntl][3]) * w1;
        }
    }

    pA0 += __shfl_xor_sync(0xffffffffu, pA0, 1);
    pA0 += __shfl_xor_sync(0xffffffffu, pA0, 2);
    pA8 += __shfl_xor_sync(0xffffffffu, pA8, 1);
    pA8 += __shfl_xor_sync(0xffffffffu, pA8, 2);
    pB0 += __shfl_xor_sync(0xffffffffu, pB0, 1);
    pB0 += __shfl_xor_sync(0xffffffffu, pB0, 2);
    pB8 += __shfl_xor_sync(0xffffffffu, pB8, 1);
    pB8 += __shfl_xor_sync(0xffffffffu, pB8, 2);
    if (qt == 0) {
        int nA = m0 + mrowA, nB = m0 + mrowB;
        float prA0 = g_ezwe[nA]     + pA0 + q_tab[z[nA]];
        float prA8 = g_ezwe[nA + 8] + pA8 + q_tab[z[nA + 8]];
        float prB0 = g_ezwe[nB]     + pB0 + q_tab[z[nB]];
        float prB8 = g_ezwe[nB + 8] + pB8 + q_tab[z[nB + 8]];
        size_t a0 = (size_t)nA * 3, a8 = (size_t)(nA + 8) * 3;
        size_t b0 = (size_t)nB * 3, b8 = (size_t)(nB + 8) * 3;
        g_xyzq[nA]     = make_float4(xyz[a0], xyz[a0+1], xyz[a0+2], prA0);
        g_xyzq[nA + 8] = make_float4(xyz[a8], xyz[a8+1], xyz[a8+2], prA8);
        g_xyzq[nB]     = make_float4(xyz[b0], xyz[b0+1], xyz[b0+2], prB0);
        g_xyzq[nB + 8] = make_float4(xyz[b8], xyz[b8+1], xyz[b8+2], prB8);
    }
}

// ---------------- K4: correction + O(A^2) Coulomb (R12 exact, frozen) ---------
#define ROFF2C 14.0625f
#define CAPL 24   // stash entries per lane

__device__ __forceinline__ float flush_smem(const float4* sp, uint32_t* wstash,
                                            int lane, int& scnt) {
    float e = 0.f;
    for (int s = 0; s < scnt; s++) {
        uint32_t vv = wstash[s*32 + lane];
        int j = vv >> 10, i = vv & 1023;
        float4 pi = sp[i], pj = sp[j];
        float dx = pi.x-pj.x, dy = pi.y-pj.y, dz = pi.z-pj.z;
        float r2 = dx*dx + dy*dy + dz*dz;
        float rinv = rsqa(r2);
        float r = r2 * rinv;
        float arg = (r - 1.25f) * 0.4f;
        arg = fminf(fmaxf(arg, 1e-7f), 1.f - 1e-7f);
        float num = __expf(__fdividef(-1.f, 1.f - arg));
        float den = __expf(__fdividef(-1.f, arg));
        float fs  = __fdividef(num, num + den);
        e += pi.w * pj.w * fs * (rsqa(r2 + 1.f) - rinv);
    }
    scnt = 0;
    return e;
}

__global__ void __launch_bounds__(128, 4)
k4_pair(const float* __restrict__ charge, float* __restrict__ out) {
    int b = blockIdx.y, t = blockIdx.x, tid = threadIdx.x;
    __shared__ float4 sp[AA];
    __shared__ uint32_t s_stash[4*32*CAPL];      // [wid][entry][lane]
    __shared__ float s_red[128];
    float psum = 0.f;
    // packed prologue: one LDG.128 per atom
    #pragma unroll
    for (int it = 0; it < 8; it++) {
        int a = tid + it*128;
        float4 v = g_xyzq[b*AA + a];
        sp[a] = v;
        psum += v.w;
    }
    s_red[tid] = psum; __syncthreads();
    for (int off = 64; off > 0; off >>= 1) {
        if (tid < off) s_red[tid] += s_red[tid + off];
        __syncthreads();
    }
    float corr = (charge[b] - s_red[0]) * (1.0f / AA);
    __syncthreads();
    for (int a = tid; a < AA; a += 128) sp[a].w += corr;
    __syncthreads();

    int wid = tid >> 5, lane = tid & 31;
    int wglob = t*4 + wid;                 // 0..63
    uint32_t* wstash = s_stash + wid*(32*CAPL);
    int scnt = 0;
    float e0 = 0.f;

    #pragma unroll 1
    for (int tt = 0; tt < 2; tt++) {
        int base = (tt == 0) ? (wglob * 8) : (1016 - wglob * 8);
        float xi[8], yi[8], zi[8], qi[8];
        #pragma unroll
        for (int r = 0; r < 8; r++) {
            float4 p = sp[base + r];
            xi[r] = p.x; yi[r] = p.y; zi[r] = p.z; qi[r] = p.w;
        }
        float facc[8];
        #pragma unroll
        for (int r = 0; r < 8; r++) facc[r] = 0.f;

        // intra-tile corner (28 pairs)
        {
            bool lv = (lane >= 1) && (lane < 8);
            int jc = base + (lv ? lane : 0);
            float4 pj = sp[jc];
            #pragma unroll
            for (int r = 0; r < 8; r++) {
                bool val = lv && (lane > r);
                float dx = xi[r]-pj.x, dy = yi[r]-pj.y, dz = zi[r]-pj.z;
                float r2 = dx*dx + dy*dy + dz*dz;
                float r2s = val ? r2 : 1.0f;
                float qv  = val ? pj.w : 0.0f;
                facc[r] = fmaf(qv, rsqa(r2s), facc[r]);
                if (val && r2 < ROFF2C) { wstash[scnt*32 + lane] = ((uint32_t)jc << 10) | (uint32_t)(base + r); scnt++; }
            }
        }
        // main sweep: lanes stream distinct j, 8-row register tile, factored acc
        for (int j = base + 8 + lane; j < AA; j += 32) {
            float4 pj = sp[j];
            uint32_t jp = ((uint32_t)j << 10) + (uint32_t)base;
            #pragma unroll
            for (int r = 0; r < 8; r++) {
                float dx = xi[r]-pj.x, dy = yi[r]-pj.y, dz = zi[r]-pj.z;
                float r2 = dx*dx + dy*dy + dz*dz;
                facc[r] = fmaf(pj.w, rsqa(r2), facc[r]);
                if (r2 < ROFF2C) { wstash[scnt*32 + lane] = jp + (uint32_t)r; scnt++; }
            }
            if (scnt >= CAPL - 8) e0 += flush_smem(sp, wstash, lane, scnt);  // ~never taken
        }
        #pragma unroll
        for (int r = 0; r < 8; r++) e0 = fmaf(qi[r], facc[r], e0);
    }
    e0 += flush_smem(sp, wstash, lane, scnt);

    s_red[tid] = e0; __syncthreads();
    for (int off = 64; off > 0; off >>= 1) {
        if (tid < off) s_red[tid] += s_red[tid + off];
        __syncthreads();
    }
    if (tid == 0) {
        g_partial[b*16 + t] = s_red[0];
        __threadfence();
        int done = atomicAdd(&g_cnt[b], 1);
        if (done == 15) {   // last block of this molecule: deterministic fixed-order sum
            volatile float* gp = g_partial;
            float s = 0.f;
            #pragma unroll
            for (int q = 0; q < 16; q++) s += gp[b*16 + q];
            out[b] = 332.0636f * s;
        }
    }
}

extern "C" void kernel_launch(void* const* d_in, const int* in_sizes, int n_in,
                              void* d_out, int out_size) {
    const float* e_z     = (const float*)d_in[0];
    const float* charge  = (const float*)d_in[1];
    const float* xyz     = (const float*)d_in[2];
    const float* W_lin   = (const float*)d_in[3];
    const float* b_lin   = (const float*)d_in[4];
    const float* k_plus  = (const float*)d_in[5];
    const float* k_minus = (const float*)d_in[6];
    const float* v_plus  = (const float*)d_in[7];
    const float* v_minus = (const float*)d_in[8];
    const float* Wr1     = (const float*)d_in[9];
    const float* Wr2     = (const float*)d_in[10];
    const float* Wout    = (const float*)d_in[11];
    const float* w_e     = (const float*)d_in[12];
    const float* q_tab   = (const float*)d_in[13];
    const int*   z       = (const int*)d_in[14];
    float* out = (float*)d_out;

    cudaFuncSetAttribute(k2_mma, cudaFuncAttributeMaxDynamicSharedMemorySize, K2_SMEM);

    k0f<<<129, 256>>>(W_lin, b_lin, k_plus, k_minus, Wout, w_e);
    k1_fused<<<192, 256>>>(e_z, charge, w_e, Wr1, Wr2);
    k2_mma<<<NN/128, 128, K2_SMEM>>>(charge, z, q_tab, v_plus, v_minus, xyz);
    dim3 g4(16, BB);
    k4_pair<<<g4, 128>>>(charge, out);
}